// round 8
// baseline (speedup 1.0000x reference)
#include <cuda_runtime.h>

// ---------------------------------------------------------------------------
// CML2DWithStats, fused temporal-blocking kernel (Round 8).
// Geometry identical to Round 6 (197us best): one CTA per (batch*chan,
// 32-row band); 66-logical-row x 264-col double-buffered smem window
// (139 KB); shrinking cone [s+1, 62-s]; quad row ownership with register
// rolling.
//
// Round-8 change (latency-bound: R7 showed fewer instructions != faster,
// issue 59%, occ 24% pinned by 512thr x 120regs = full regfile):
// 1024 threads/CTA with 2-column x-groups. Same total work and same
// per-pixel instruction count, but 32 warps instead of 16. Register diet
// to <=64/thread: windows 12, stats 16, drive reloaded per step via __ldg
// (L1-resident, 15x reuse) instead of register-resident.
// ---------------------------------------------------------------------------

#define SSTR  264                      // smem row stride (floats)
#define LROWS 66                       // logical rows -1..64 (physical 0..65)
#define NBUF  (LROWS * SSTR)           // 17424 floats per buffer
#define PL    8388608L                 // elements per output plane

// mapped[x0-1 .. x0+2] for one row: one LDS.64 + 2 shuffles; edge lanes
// read the in-row halo columns via scalar LDS (pad cols exist both sides).
__device__ __forceinline__ void load4(const float* __restrict__ p, int lane, float m[4]) {
    float2 v = *reinterpret_cast<const float2*>(p);
    float left  = __shfl_up_sync(0xffffffffu, v.y, 1);
    float right = __shfl_down_sync(0xffffffffu, v.x, 1);
    if (lane == 0)  left  = p[-1];
    if (lane == 31) right = p[2];
    m[0] = left; m[1] = v.x; m[2] = v.y; m[3] = right;
}

// Folded update for 2 columns: g = sum(W .* mapped_nbr) + 0.15*drive, clamped.
__device__ __forceinline__ void taps(const float* __restrict__ W,
                                     const float A[4], const float B[4],
                                     const float C[4], float d0, float d1,
                                     float g[2]) {
    #pragma unroll
    for (int j = 0; j < 2; ++j) {
        float t =      W[0] * A[j];
        t = fmaf(W[1], A[j + 1], t);
        t = fmaf(W[2], A[j + 2], t);
        t = fmaf(W[3], B[j],     t);
        t = fmaf(W[4], B[j + 1], t);
        t = fmaf(W[5], B[j + 2], t);
        t = fmaf(W[6], C[j],     t);
        t = fmaf(W[7], C[j + 1], t);
        t = fmaf(W[8], C[j + 2], t);
        t = fmaf(0.15f, (j == 0 ? d0 : d1), t);
        g[j] = fminf(fmaxf(t, 1e-4f), 1.0f - 1e-4f);
    }
}

// Halo block: 4 contiguous rows from R0, predicated by cone + image bounds.
// Predicates warp-uniform (ty-derived R0, uniform lo/hi/y0). Stale rows
// outside [lo-1,hi+1] never feed computed rows (cone invariant).
__device__ __forceinline__ void halo_block(
    const float* __restrict__ srcb, float* __restrict__ dstb,
    int R0, int lo, int hi, int lane, int x0, int y0,
    const float* __restrict__ dpl, const float* __restrict__ W)
{
    if (R0 > hi || R0 + 3 < lo) return;
    const int yb = y0 - 16 + R0;
    if (yb + 3 < 0 || yb > 255) return;

    const float* pA = srcb + (R0 - 1) * SSTR + 4 + x0;
    float A[4], B[4], C[4];
    load4(pA,        lane, A);
    load4(pA + SSTR, lane, B);
    #pragma unroll
    for (int i = 0; i < 4; ++i) {
        load4(pA + (i + 2) * SSTR, lane, C);
        const int r = R0 + i;
        const int y = yb + i;
        if (r >= lo && r <= hi && y >= 0 && y <= 255) {
            const float2 d2 = __ldg(reinterpret_cast<const float2*>(dpl + y * 256 + x0));
            float g[2];
            taps(W, A, B, C, d2.x, d2.y, g);
            float2 mv;
            mv.x = (3.9f * g[0]) * (1.0f - g[0]);
            mv.y = (3.9f * g[1]) * (1.0f - g[1]);
            *reinterpret_cast<float2*>(dstb + r * SSTR + 4 + x0) = mv;
        }
        #pragma unroll
        for (int q = 0; q < 4; ++q) { A[q] = B[q]; B[q] = C[q]; }
    }
}

// Interior block: rows [R0,R0+3] subset of [16,47]; always in-cone ->
// unconditional. Drive re-read per step via __ldg (L1-resident).
template<bool LAST>
__device__ __forceinline__ void int_block(
    const float* __restrict__ srcb, float* __restrict__ dstb,
    int R0, int lane, int x0, int y0,
    const float* __restrict__ dpl, const float* __restrict__ W,
    float (&sum)[4][2], float (&sq)[4][2], float* __restrict__ outBase)
{
    const float* pA = srcb + (R0 - 1) * SSTR + 4 + x0;
    float A[4], B[4], C[4];
    load4(pA,        lane, A);
    load4(pA + SSTR, lane, B);
    #pragma unroll
    for (int i = 0; i < 4; ++i) {
        load4(pA + (i + 2) * SSTR, lane, C);
        const int y = y0 + (R0 - 16) + i;
        const float2 d2 = __ldg(reinterpret_cast<const float2*>(dpl + y * 256 + x0));
        float g[2];
        taps(W, A, B, C, d2.x, d2.y, g);
        sum[i][0] += g[0];
        sum[i][1] += g[1];
        sq[i][0]   = fmaf(g[0], g[0], sq[i][0]);
        sq[i][1]   = fmaf(g[1], g[1], sq[i][1]);
        if (!LAST) {
            float2 mv;
            mv.x = (3.9f * g[0]) * (1.0f - g[0]);
            mv.y = (3.9f * g[1]) * (1.0f - g[1]);
            *reinterpret_cast<float2*>(dstb + (R0 + i) * SSTR + 4 + x0) = mv;
        } else {
            const long o = (long)y * 256 + x0;
            *reinterpret_cast<float2*>(outBase + o) = make_float2(g[0], g[1]);
            const float2 dl = make_float2(g[0] - d2.x, g[1] - d2.y);
            *reinterpret_cast<float2*>(outBase + 3L * PL + o) = dl;
            *reinterpret_cast<float2*>(outBase + 4L * PL + o) = dl;
        }
        #pragma unroll
        for (int q = 0; q < 4; ++q) { A[q] = B[q]; B[q] = C[q]; }
    }
}

__global__ void __launch_bounds__(1024, 1)
cml_fused_kernel(const float* __restrict__ drive,
                 const float* __restrict__ Kl,
                 float* __restrict__ out)
{
    extern __shared__ float smem[];
    float* b0 = smem + SSTR;           // logical row 0 of buffer 0
    float* b1 = smem + NBUF + SSTR;    // logical row 0 of buffer 1

    const int tile = blockIdx.x;       // (b*8 + c)*8 + band
    const int band = tile & 7;
    const int bc   = tile >> 3;
    const int ch   = bc & 7;
    const int y0   = band * 32;
    const float* dpl     = drive + (long)bc * 65536L;
    float*       outBase = out   + (long)bc * 65536L;

    const int tid  = threadIdx.x;
    const int tx   = tid & 127;        // x group (2 columns)
    const int ty   = tid >> 7;         // 0..7, warp-uniform (warps don't straddle)
    const int lane = tid & 31;
    const int x0   = tx << 1;

    // Block ownership: interior quad Ri in [16,47]; halo quad Rh outside.
    const int Ri = (ty < 4) ? (32 + 4 * ty) : (16 + 4 * (ty - 4));
    const int Rh = (ty < 4) ? (4 * ty)      : (48 + 4 * (ty - 4));

    // Folded conv weights: W = 0.255*K, +0.595 at center.
    float W[9];
    #pragma unroll
    for (int i = 0; i < 9; ++i) W[i] = 0.255f * __ldg(&Kl[ch * 9 + i]);
    W[4] += 0.595f;

    // Zero both buffers (guards + out-of-image rows = conv zero padding).
    for (int i = tid; i < 2 * NBUF; i += 1024) smem[i] = 0.0f;
    __syncthreads();

    // Init buffer 0 with mapped(drive) on logical rows 1..62 (valid y only).
    for (int idx = tid; idx < 62 * 64; idx += 1024) {
        const int r  = 1 + (idx >> 6);
        const int xg = (idx & 63) << 2;
        const int y  = y0 - 16 + r;
        if (y >= 0 && y < 256) {
            const float4 d = *reinterpret_cast<const float4*>(dpl + y * 256 + xg);
            float4 m;
            m.x = (3.9f * d.x) * (1.0f - d.x);
            m.y = (3.9f * d.y) * (1.0f - d.y);
            m.z = (3.9f * d.z) * (1.0f - d.z);
            m.w = (3.9f * d.w) * (1.0f - d.w);
            *reinterpret_cast<float4*>(b0 + r * SSTR + 4 + xg) = m;
        }
    }
    __syncthreads();

    float sum[4][2], sq[4][2];
    #pragma unroll
    for (int i = 0; i < 4; ++i) {
        sum[i][0] = 0.0f; sum[i][1] = 0.0f;
        sq[i][0]  = 0.0f; sq[i][1]  = 0.0f;
    }

    const float* src = b0;
    float*       dst = b1;
    for (int s = 1; s <= 14; ++s) {
        const int lo = s + 1, hi = 62 - s;
        halo_block(src, dst, Rh, lo, hi, lane, x0, y0, dpl, W);
        int_block<false>(src, dst, Ri, lane, x0, y0, dpl, W, sum, sq, outBase);
        const float* t = src; src = dst; dst = const_cast<float*>(t);
        __syncthreads();
    }
    // Step 15: cone == interior; halo quads fully outside -> skipped.
    int_block<true>(src, dst, Ri, lane, x0, y0, dpl, W, sum, sq, outBase);

    // mean / var from register accumulators.
    const float inv15 = 1.0f / 15.0f;
    #pragma unroll
    for (int i = 0; i < 4; ++i) {
        const int y = y0 + (Ri - 16) + i;
        const long o = (long)y * 256 + x0;
        float2 mn, vr;
        mn.x = sum[i][0] * inv15;
        mn.y = sum[i][1] * inv15;
        vr.x = fmaf(-mn.x, mn.x, sq[i][0] * inv15);
        vr.y = fmaf(-mn.y, mn.y, sq[i][1] * inv15);
        *reinterpret_cast<float2*>(outBase + 1L * PL + o) = mn;
        *reinterpret_cast<float2*>(outBase + 2L * PL + o) = vr;
    }
}

extern "C" void kernel_launch(void* const* d_in, const int* in_sizes, int n_in,
                              void* d_out, int out_size)
{
    const float* drive = (const float*)d_in[0];
    const float* Kl    = (const float*)d_in[1];
    if (n_in >= 2 && in_sizes[0] == 72) {         // defensive input-order check
        const float* t = drive; drive = Kl; Kl = t;
    }
    float* out = (float*)d_out;
    (void)out_size;

    const size_t shmem = 2 * NBUF * sizeof(float);   // 139392 bytes
    cudaFuncSetAttribute(cml_fused_kernel,
                         cudaFuncAttributeMaxDynamicSharedMemorySize, (int)shmem);
    cml_fused_kernel<<<1024, 1024, shmem>>>(drive, Kl, out);
}